// round 6
// baseline (speedup 1.0000x reference)
#include <cuda_runtime.h>
#include <cstdint>
#include <math_constants.h>

// NearestEmbed, filter-then-rerank:
//   stage 1: 1-pass tf32 mma.sync GEMM (approx scores, rigorous error bound)
//   stage 2: exact double-precision re-rank of candidates within the bound
// score[n,k] = ||e_k||^2 - 2 * x_n . e_k

#define D_DIM 256
#define K_DIM 1024
#define BM 128
#define BN 128
#define DC 32
#define NKT (K_DIM / BN)
#define NCH (D_DIM / DC)
#define THREADS 512
#define CAP 4096

#define TILE_FLOATS (DC * BM)            // 4096 floats = 16KB
#define BUF_FLOATS (2 * TILE_FLOATS)     // AH, BH
#define SMEM_DYN (2 * BUF_FLOATS * 4)    // 65536 bytes

__device__ float g_e2[K_DIM];
__device__ int g_emax_bits;              // max ||e_k||^2 as float bits (all positive)
__device__ float g_xn2[64 * 1024];       // ||x_n||^2
__device__ float g_xT[64 * 1024 * 256];  // x transposed: [n][d] contiguous
__device__ float g_eT[K_DIM * D_DIM];    // emb transposed: [k][d] contiguous

__device__ __forceinline__ uint32_t to_tf32(float f) {
    uint32_t r;
    asm("cvt.rna.tf32.f32 %0, %1;" : "=r"(r) : "f"(f));
    return r;
}

__device__ __forceinline__ void mma8(float* c, const uint32_t* a, const uint32_t* b) {
    asm volatile(
        "mma.sync.aligned.m16n8k8.row.col.f32.tf32.tf32.f32 "
        "{%0,%1,%2,%3}, {%4,%5,%6,%7}, {%8,%9}, {%0,%1,%2,%3};"
        : "+f"(c[0]), "+f"(c[1]), "+f"(c[2]), "+f"(c[3])
        : "r"(a[0]), "r"(a[1]), "r"(a[2]), "r"(a[3]), "r"(b[0]), "r"(b[1]));
}

// ---------------- prep kernels ----------------
__global__ void e2_kernel(const float* __restrict__ emb) {
    int k = blockIdx.x * blockDim.x + threadIdx.x;
    float s = 0.f;
#pragma unroll 8
    for (int d = 0; d < D_DIM; ++d) {
        float v = emb[(size_t)d * K_DIM + k];
        s = fmaf(v, v, s);
    }
    g_e2[k] = s;
    atomicMax(&g_emax_bits, __float_as_int(s));
}

// x (64,256,1024) -> xT (65536, 256); tiled transpose, 32x32 per block
__global__ void xt_kernel(const float* __restrict__ x) {
    __shared__ float t[32][33];
    const int b = blockIdx.z;
    const int d0 = blockIdx.y * 32;
    const int hw0 = blockIdx.x * 32;
    const int tx = threadIdx.x, ty = threadIdx.y;
#pragma unroll
    for (int i = 0; i < 4; ++i) {
        int d = d0 + ty + i * 8;
        t[ty + i * 8][tx] = x[((size_t)b * D_DIM + d) * 1024 + hw0 + tx];
    }
    __syncthreads();
#pragma unroll
    for (int i = 0; i < 4; ++i) {
        int n = b * 1024 + hw0 + ty + i * 8;
        g_xT[(size_t)n * D_DIM + d0 + tx] = t[tx][ty + i * 8];
    }
}

// emb (256,1024) -> eT (1024,256)
__global__ void et_kernel(const float* __restrict__ emb) {
    __shared__ float t[32][33];
    const int d0 = blockIdx.y * 32;
    const int k0 = blockIdx.x * 32;
    const int tx = threadIdx.x, ty = threadIdx.y;
#pragma unroll
    for (int i = 0; i < 4; ++i)
        t[ty + i * 8][tx] = emb[(size_t)(d0 + ty + i * 8) * K_DIM + k0 + tx];
    __syncthreads();
#pragma unroll
    for (int i = 0; i < 4; ++i)
        g_eT[(size_t)(k0 + ty + i * 8) * D_DIM + d0 + tx] = t[tx][ty + i * 8];
}

// ||x_n||^2 from xT (coalesced): one warp per n
__global__ void xn2_kernel() {
    int w = (blockIdx.x * blockDim.x + threadIdx.x) >> 5;
    int lane = threadIdx.x & 31;
    const float* r = g_xT + (size_t)w * D_DIM;
    float s = 0.f;
#pragma unroll
    for (int d = lane; d < D_DIM; d += 32) {
        float v = r[d];
        s = fmaf(v, v, s);
    }
#pragma unroll
    for (int off = 16; off > 0; off >>= 1) s += __shfl_xor_sync(0xFFFFFFFFu, s, off);
    if (lane == 0) g_xn2[w] = s;
}

// ---------------- main kernel ----------------
__device__ __forceinline__ void stage(float* __restrict__ buf, int dt, int k0,
                                      const float* __restrict__ xb,
                                      const float* __restrict__ emb, int tid) {
#pragma unroll
    for (int i = 0; i < 2; ++i) {
        int f = tid + i * THREADS;
        int kk = f >> 5;
        int q = f & 31;
        int w = kk * 128 + ((4 * q) ^ ((kk & 3) << 3));
        float4 va = *(const float4*)(xb + (size_t)(dt + kk) * 1024 + 4 * q);
        float4 vb = *(const float4*)(emb + (size_t)(dt + kk) * K_DIM + k0 + 4 * q);
        uint4 ha = make_uint4(to_tf32(va.x), to_tf32(va.y), to_tf32(va.z), to_tf32(va.w));
        uint4 hb = make_uint4(to_tf32(vb.x), to_tf32(vb.y), to_tf32(vb.z), to_tf32(vb.w));
        *(uint4*)(buf + w) = ha;
        *(uint4*)(buf + TILE_FLOATS + w) = hb;
    }
}

__global__ __launch_bounds__(THREADS, 1)
void vq_mma_kernel(const float* __restrict__ emb, float* __restrict__ out,
                   float* __restrict__ idx_out, int has_idx) {
    extern __shared__ float sm[];
    __shared__ float e2s[K_DIM];
    __shared__ float redv[BM][4];
    __shared__ float runmin[BM];
    __shared__ float marg[BM];
    __shared__ int cand[CAP];
    __shared__ int cand_cnt;
    __shared__ unsigned long long umin[BM];
    __shared__ int kwin[BM];

    const int tid = threadIdx.x;
    const int wid = tid >> 5;
    const int lane = tid & 31;
    const int gid = lane >> 2;
    const int tig = lane & 3;
    const int wm = wid >> 2;
    const int wn = wid & 3;
    const int mbw = wm * 32;
    const int nbw = wn * 32;
    const int sw = tig << 3;

    const int n0 = blockIdx.x * BM;
    const int b = n0 >> 10;
    const int hw0 = n0 & 1023;
    const float* xb = /* x in original layout via xT? no: use gmem x strided */ nullptr;
    // we stage from the ORIGINAL x layout; recover pointer via xT? Original x is
    // not passed; stage from g_xT instead (rows are contiguous per latent, but we
    // need [d][m] ordering). Simplest: stage A from g_xT transposed reads would be
    // uncoalesced; instead pass x as an extra arg. (set below)
    (void)xb;

    if (tid == 0) cand_cnt = 0;
    for (int i = tid; i < K_DIM; i += THREADS) e2s[i] = g_e2[i];
    {
        const float semax = sqrtf(__int_as_float(g_emax_bits));
        for (int i = tid; i < BM; i += THREADS) {
            marg[i] = 0.00390625f * sqrtf(g_xn2[n0 + i]) * semax + 4e-3f;
            runmin[i] = CUDART_INF_F;
            umin[i] = ~0ULL;
        }
    }
    __syncthreads();

    float best[4];
#pragma unroll
    for (int s = 0; s < 4; ++s) best[s] = CUDART_INF_F;

    const float* xsrc = out;  // placeholder; real pointer set by caller trick below
    (void)xsrc;

    for (int kt = 0; kt < NKT; ++kt) {
        const int k0 = kt * BN;
        float acc[2][4][4];
#pragma unroll
        for (int mt = 0; mt < 2; ++mt)
#pragma unroll
            for (int nt = 0; nt < 4; ++nt)
#pragma unroll
                for (int j = 0; j < 4; ++j) acc[mt][nt][j] = 0.f;

        // A source: xT rows are [n][d]; we need [d][m] tiles. Use xT with
        // swapped roles: load via d-major reads from xT would be strided.
        // Instead stage A from xT directly: element (d, m) = xT[(n0+m)*256 + d].
        // Column reads of xT are coalesced across m for fixed d? stride 256 floats
        // -> NOT coalesced. So we keep using xT but read m-major: thread f maps to
        // (m, d4) instead of (d, q):
        __syncthreads();
        {
            float* buf = sm;
            // A: 128 m-rows x 32 d each; thread handles one (m, 16B d-chunk)
#pragma unroll
            for (int i = 0; i < 2; ++i) {
                int f = tid + i * THREADS;       // 0..1023
                int m = f & 127;                  // latent row
                int dq = f >> 7;                  // 0..7 -> d4 chunk
                float4 va = *(const float4*)(g_xT + (size_t)(n0 + m) * D_DIM + 0 * DC + dq * 4);
                (void)va;
            }
        }
        // (the real staging below in the chunk loop)

        for (int ch = 0; ch < NCH; ++ch) {
            float* cur = sm + (ch & 1) * BUF_FLOATS;
            if (ch == 0 && kt == 0) {
                // first chunk of first tile: fill synchronously
            }
            // stage current chunk on first iteration, next chunk otherwise
            if (ch == 0) {
                // fill buffer 0 for this tile
                {
                    int dt = 0;
#pragma unroll
                    for (int i = 0; i < 2; ++i) {
                        int f = tid + i * THREADS;
                        int m = f & 127;
                        int dq = f >> 7;
                        int kk4 = dq;  // 4-float group within DC=32 -> dq*4 .. dq*4+3
                        float4 va = *(const float4*)(g_xT + (size_t)(n0 + m) * D_DIM + dt + kk4 * 4);
                        // scatter 4 floats to 4 different k-rows of the smem tile
                        uint32_t h0 = to_tf32(va.x), h1 = to_tf32(va.y), h2 = to_tf32(va.z), h3 = to_tf32(va.w);
                        int kkb = kk4 * 4;
                        sm[(kkb + 0) * 128 + (m ^ (((kkb + 0) & 3) << 3))] = __uint_as_float(h0);
                        sm[(kkb + 1) * 128 + (m ^ (((kkb + 1) & 3) << 3))] = __uint_as_float(h1);
                        sm[(kkb + 2) * 128 + (m ^ (((kkb + 2) & 3) << 3))] = __uint_as_float(h2);
                        sm[(kkb + 3) * 128 + (m ^ (((kkb + 3) & 3) << 3))] = __uint_as_float(h3);
                    }
                    // B tile from emb (d-major, coalesced)
#pragma unroll
                    for (int i = 0; i < 2; ++i) {
                        int f = tid + i * THREADS;
                        int kk = f >> 5;
                        int q = f & 31;
                        int w = kk * 128 + ((4 * q) ^ ((kk & 3) << 3));
                        float4 vb = *(const float4*)(emb + (size_t)(dt + kk) * K_DIM + k0 + 4 * q);
                        uint4 hb = make_uint4(to_tf32(vb.x), to_tf32(vb.y), to_tf32(vb.z), to_tf32(vb.w));
                        *(uint4*)(sm + TILE_FLOATS + w) = hb;
                    }
                }
                __syncthreads();
            }
            if (ch + 1 < NCH) {
                float* nxt = sm + ((ch + 1) & 1) * BUF_FLOATS;
                int dt = (ch + 1) * DC;
#pragma unroll
                for (int i = 0; i < 2; ++i) {
                    int f = tid + i * THREADS;
                    int m = f & 127;
                    int dq = f >> 7;
                    float4 va = *(const float4*)(g_xT + (size_t)(n0 + m) * D_DIM + dt + dq * 4);
                    uint32_t h0 = to_tf32(va.x), h1 = to_tf32(va.y), h2 = to_tf32(va.z), h3 = to_tf32(va.w);
                    int kkb = dq * 4;
                    nxt[(kkb + 0) * 128 + (m ^ (((kkb + 0) & 3) << 3))] = __uint_as_float(h0);
                    nxt[(kkb + 1) * 128 + (m ^ (((kkb + 1) & 3) << 3))] = __uint_as_float(h1);
                    nxt[(kkb + 2) * 128 + (m ^ (((kkb + 2) & 3) << 3))] = __uint_as_float(h2);
                    nxt[(kkb + 3) * 128 + (m ^ (((kkb + 3) & 3) << 3))] = __uint_as_float(h3);
                }
#pragma unroll
                for (int i = 0; i < 2; ++i) {
                    int f = tid + i * THREADS;
                    int kk = f >> 5;
                    int q = f & 31;
                    int w = kk * 128 + ((4 * q) ^ ((kk & 3) << 3));
                    float4 vb = *(const float4*)(emb + (size_t)(dt + kk) * K_DIM + k0 + 4 * q);
                    uint4 hb = make_uint4(to_tf32(vb.x), to_tf32(vb.y), to_tf32(vb.z), to_tf32(vb.w));
                    *(uint4*)(nxt + TILE_FLOATS + w) = hb;
                }
            }

            const float* AH = cur;
            const float* BH = cur + TILE_FLOATS;
#pragma unroll
            for (int g = 0; g < 4; ++g) {
                const int kkA = g * 8 + tig;
                uint32_t ahi[2][4];
#pragma unroll
                for (int mt = 0; mt < 2; ++mt) {
                    const int M0 = mbw + mt * 16 + gid;
                    ahi[mt][0] = __float_as_uint(AH[kkA * 128 + (M0 ^ sw)]);
                    ahi[mt][1] = __float_as_uint(AH[kkA * 128 + ((M0 + 8) ^ sw)]);
                    ahi[mt][2] = __float_as_uint(AH[(kkA + 4) * 128 + (M0 ^ sw)]);
                    ahi[mt][3] = __float_as_uint(AH[(kkA + 4) * 128 + ((M0 + 8) ^ sw)]);
                }
#pragma unroll
                for (int nt = 0; nt < 4; ++nt) {
                    const int n = nbw + nt * 8 + gid;
                    uint32_t bh[2];
                    bh[0] = __float_as_uint(BH[kkA * 128 + (n ^ sw)]);
                    bh[1] = __float_as_uint(BH[(kkA + 4) * 128 + (n ^ sw)]);
                    mma8(acc[0][nt], ahi[0], bh);
                    mma8(acc[1][nt], ahi[1], bh);
                }
            }
            __syncthreads();
        }

        // scores in place; update running best
#pragma unroll
        for (int mt = 0; mt < 2; ++mt)
#pragma unroll
            for (int nt = 0; nt < 4; ++nt) {
                const int kc = k0 + nbw + nt * 8 + 2 * tig;
                acc[mt][nt][0] = fmaf(-2.f, acc[mt][nt][0], e2s[kc]);
                acc[mt][nt][1] = fmaf(-2.f, acc[mt][nt][1], e2s[kc + 1]);
                acc[mt][nt][2] = fmaf(-2.f, acc[mt][nt][2], e2s[kc]);
                acc[mt][nt][3] = fmaf(-2.f, acc[mt][nt][3], e2s[kc + 1]);
                float m0 = fminf(acc[mt][nt][0], acc[mt][nt][1]);
                float m1 = fminf(acc[mt][nt][2], acc[mt][nt][3]);
                best[2 * mt] = fminf(best[2 * mt], m0);
                best[2 * mt + 1] = fminf(best[2 * mt + 1], m1);
            }

        // running-min reduce
#pragma unroll
        for (int s = 0; s < 4; ++s) {
            float v = best[s];
#pragma unroll
            for (int off = 1; off <= 2; off <<= 1)
                v = fminf(v, __shfl_xor_sync(0xFFFFFFFFu, v, off));
            if (tig == 0) {
                int row = mbw + (s >> 1) * 16 + gid + (s & 1) * 8;
                redv[row][wn] = v;
            }
        }
        __syncthreads();
        if (tid < BM)
            runmin[tid] = fminf(fminf(redv[tid][0], redv[tid][1]),
                                fminf(redv[tid][2], redv[tid][3]));
        __syncthreads();

        // candidate scan for this tile
#pragma unroll
        for (int mt = 0; mt < 2; ++mt) {
            const int r0 = mbw + mt * 16 + gid;
            const float t0 = runmin[r0] + marg[r0];
            const float t1 = runmin[r0 + 8] + marg[r0 + 8];
#pragma unroll
            for (int nt = 0; nt < 4; ++nt) {
                const int kc = k0 + nbw + nt * 8 + 2 * tig;
                if (acc[mt][nt][0] <= t0) { int p = atomicAdd(&cand_cnt, 1); if (p < CAP) cand[p] = (r0 << 10) | kc; }
                if (acc[mt][nt][1] <= t0) { int p = atomicAdd(&cand_cnt, 1); if (p < CAP) cand[p] = (r0 << 10) | (kc + 1); }
                if (acc[mt][nt][2] <= t1) { int p = atomicAdd(&cand_cnt, 1); if (p < CAP) cand[p] = ((r0 + 8) << 10) | kc; }
                if (acc[mt][nt][3] <= t1) { int p = atomicAdd(&cand_cnt, 1); if (p < CAP) cand[p] = ((r0 + 8) << 10) | (kc + 1); }
            }
        }
        __syncthreads();
    }

    // exact double-precision re-rank of candidates
    {
        int cnt = cand_cnt;
        if (cnt > CAP) cnt = CAP;
        for (int i = tid; i < cnt; i += THREADS) {
            int c = cand[i];
            int row = c >> 10;
            int k = c & 1023;
            const float* xr = g_xT + (size_t)(n0 + row) * D_DIM;
            const float* er = g_eT + (size_t)k * D_DIM;
            double s0 = 0.0, s1 = 0.0, s2 = 0.0, s3 = 0.0;
#pragma unroll 4
            for (int d = 0; d < D_DIM; d += 4) {
                float4 xv = *(const float4*)(xr + d);
                float4 ev = *(const float4*)(er + d);
                s0 = fma((double)ev.x, (double)ev.x - 2.0 * (double)xv.x, s0);
                s1 = fma((double)ev.y, (double)ev.y - 2.0 * (double)xv.y, s1);
                s2 = fma((double)ev.z, (double)ev.z - 2.0 * (double)xv.z, s2);
                s3 = fma((double)ev.w, (double)ev.w - 2.0 * (double)xv.w, s3);
            }
            double sc = (s0 + s1) + (s2 + s3);
            long long bits = __double_as_longlong(sc);
            unsigned long long u = (unsigned long long)bits;
            u ^= (bits < 0) ? 0xFFFFFFFFFFFFFFFFULL : 0x8000000000000000ULL;
            unsigned long long v = (u & ~1023ULL) | (unsigned long long)k;
            atomicMin(&umin[row], v);
        }
    }
    __syncthreads();
    if (tid < BM) {
        int bi = (int)(umin[tid] & 1023ULL);
        kwin[tid] = bi;
        if (has_idx) idx_out[n0 + tid] = (float)bi;
    }
    __syncthreads();

    // gather nearest code (exact fp32), scatter to (B,D,H,W)
    for (int r = tid; r < D_DIM * BM; r += THREADS) {
        int d = r >> 7;
        int m = r & (BM - 1);
        out[((size_t)b * D_DIM + d) * 1024 + hw0 + m] = emb[(size_t)d * K_DIM + kwin[m]];
    }
}

extern "C" void kernel_launch(void* const* d_in, const int* in_sizes, int n_in,
                              void* d_out, int out_size) {
    const float* x = (const float*)d_in[0];    // (64,256,32,32)
    const float* emb = (const float*)d_in[1];  // (256,1024)
    float* out = (float*)d_out;

    const int n_img = 64 * 256 * 32 * 32;
    const int n_lat = 64 * 32 * 32;
    float* idx_out = nullptr;
    int has_idx = 0;
    if (out_size >= n_img + n_lat) {
        idx_out = out + n_img;
        has_idx = 1;
    }

    cudaFuncSetAttribute(vq_mma_kernel, cudaFuncAttributeMaxDynamicSharedMemorySize, SMEM_DYN);

    e2_kernel<<<4, 256>>>(emb);
    xt_kernel<<<dim3(32, 8, 64), dim3(32, 8)>>>(x);
    et_kernel<<<dim3(32, 8, 1), dim3(32, 8)>>>(emb);
    xn2_kernel<<<65536 / 8, 256>>>();
    vq_mma_kernel<<<512, THREADS, SMEM_DYN>>>(emb, out, idx_out, has_idx);
}

// round 7
// speedup vs baseline: 1.0908x; 1.0908x over previous
#include <cuda_runtime.h>
#include <cstdint>
#include <math_constants.h>

// NearestEmbed, filter-then-rerank (R7):
//   stage 1: 1-pass tf32 mma.sync GEMM, coalesced d-major staging (as R3-R5)
//   stage 2: exact double-precision re-rank of margin-bounded candidates
// score[n,k] = ||e_k||^2 - 2 * x_n . e_k

#define D_DIM 256
#define K_DIM 1024
#define BM 128
#define BN 128
#define DC 32
#define NKT (K_DIM / BN)
#define NCH (D_DIM / DC)
#define THREADS 512
#define CAP 4096

#define TILE_FLOATS (DC * BM)            // 4096 floats = 16KB
#define BUF_FLOATS (2 * TILE_FLOATS)     // A, B
#define SMEM_DYN (2 * BUF_FLOATS * 4)    // 65536 bytes

__device__ float g_e2[K_DIM];
__device__ int g_emax_bits;              // max ||e_k||^2 as float bits (positive)
__device__ float g_xn2[64 * 1024];       // ||x_n||^2
__device__ float g_xT[64 * 1024 * 256];  // x transposed: [n][d] contiguous
__device__ float g_eT[K_DIM * D_DIM];    // emb transposed: [k][d] contiguous

__device__ __forceinline__ uint32_t to_tf32(float f) {
    uint32_t r;
    asm("cvt.rna.tf32.f32 %0, %1;" : "=r"(r) : "f"(f));
    return r;
}

__device__ __forceinline__ void mma8(float* c, const uint32_t* a, const uint32_t* b) {
    asm volatile(
        "mma.sync.aligned.m16n8k8.row.col.f32.tf32.tf32.f32 "
        "{%0,%1,%2,%3}, {%4,%5,%6,%7}, {%8,%9}, {%0,%1,%2,%3};"
        : "+f"(c[0]), "+f"(c[1]), "+f"(c[2]), "+f"(c[3])
        : "r"(a[0]), "r"(a[1]), "r"(a[2]), "r"(a[3]), "r"(b[0]), "r"(b[1]));
}

// ---------------- prep kernels ----------------
__global__ void e2_kernel(const float* __restrict__ emb) {
    int k = blockIdx.x * blockDim.x + threadIdx.x;
    float s = 0.f;
#pragma unroll 8
    for (int d = 0; d < D_DIM; ++d) {
        float v = emb[(size_t)d * K_DIM + k];
        s = fmaf(v, v, s);
    }
    g_e2[k] = s;
    atomicMax(&g_emax_bits, __float_as_int(s));
}

// x (64,256,1024) -> xT (65536, 256), plus ||x_n||^2
__global__ void xt_kernel(const float* __restrict__ x) {
    __shared__ float t[32][33];
    const int b = blockIdx.z;
    const int d0 = blockIdx.y * 32;
    const int hw0 = blockIdx.x * 32;
    const int tx = threadIdx.x, ty = threadIdx.y;
#pragma unroll
    for (int i = 0; i < 4; ++i) {
        int d = d0 + ty + i * 8;
        t[ty + i * 8][tx] = x[((size_t)b * D_DIM + d) * 1024 + hw0 + tx];
    }
    __syncthreads();
#pragma unroll
    for (int i = 0; i < 4; ++i) {
        int n = b * 1024 + hw0 + ty + i * 8;
        g_xT[(size_t)n * D_DIM + d0 + tx] = t[tx][ty + i * 8];
    }
}

// emb (256,1024) -> eT (1024,256)
__global__ void et_kernel(const float* __restrict__ emb) {
    __shared__ float t[32][33];
    const int d0 = blockIdx.y * 32;
    const int k0 = blockIdx.x * 32;
    const int tx = threadIdx.x, ty = threadIdx.y;
#pragma unroll
    for (int i = 0; i < 4; ++i)
        t[ty + i * 8][tx] = emb[(size_t)(d0 + ty + i * 8) * K_DIM + k0 + tx];
    __syncthreads();
#pragma unroll
    for (int i = 0; i < 4; ++i)
        g_eT[(size_t)(k0 + ty + i * 8) * D_DIM + d0 + tx] = t[tx][ty + i * 8];
}

// ||x_n||^2 from xT (coalesced): one warp per n
__global__ void xn2_kernel() {
    int w = (blockIdx.x * blockDim.x + threadIdx.x) >> 5;
    int lane = threadIdx.x & 31;
    const float* r = g_xT + (size_t)w * D_DIM;
    float s = 0.f;
#pragma unroll
    for (int d = lane; d < D_DIM; d += 32) {
        float v = r[d];
        s = fmaf(v, v, s);
    }
#pragma unroll
    for (int off = 16; off > 0; off >>= 1) s += __shfl_xor_sync(0xFFFFFFFFu, s, off);
    if (lane == 0) g_xn2[w] = s;
}

// ---------------- main kernel ----------------
// coalesced d-major staging from original x layout + emb, tf32 in-flight
__device__ __forceinline__ void stage(float* __restrict__ buf, int dt, int k0,
                                      const float* __restrict__ xb,
                                      const float* __restrict__ emb, int tid) {
#pragma unroll
    for (int i = 0; i < 2; ++i) {
        int f = tid + i * THREADS;
        int kk = f >> 5;
        int q = f & 31;
        int w = kk * 128 + ((4 * q) ^ ((kk & 3) << 3));
        float4 va = *(const float4*)(xb + (size_t)(dt + kk) * 1024 + 4 * q);
        float4 vb = *(const float4*)(emb + (size_t)(dt + kk) * K_DIM + k0 + 4 * q);
        uint4 ha = make_uint4(to_tf32(va.x), to_tf32(va.y), to_tf32(va.z), to_tf32(va.w));
        uint4 hb = make_uint4(to_tf32(vb.x), to_tf32(vb.y), to_tf32(vb.z), to_tf32(vb.w));
        *(uint4*)(buf + w) = ha;
        *(uint4*)(buf + TILE_FLOATS + w) = hb;
    }
}

__global__ __launch_bounds__(THREADS, 1)
void vq_mma_kernel(const float* __restrict__ x, const float* __restrict__ emb,
                   float* __restrict__ out, float* __restrict__ idx_out, int has_idx) {
    extern __shared__ float sm[];
    __shared__ float e2s[K_DIM];
    __shared__ float redv[BM][4];
    __shared__ float runmin[BM];
    __shared__ float marg[BM];
    __shared__ int cand[CAP];
    __shared__ int cand_cnt;
    __shared__ unsigned long long umin[BM];
    __shared__ int kwin[BM];

    const int tid = threadIdx.x;
    const int wid = tid >> 5;
    const int lane = tid & 31;
    const int gid = lane >> 2;
    const int tig = lane & 3;
    const int wm = wid >> 2;
    const int wn = wid & 3;
    const int mbw = wm * 32;
    const int nbw = wn * 32;
    const int sw = tig << 3;

    const int n0 = blockIdx.x * BM;
    const int b = n0 >> 10;
    const int hw0 = n0 & 1023;
    const float* xb = x + (size_t)b * D_DIM * 1024 + hw0;

    if (tid == 0) cand_cnt = 0;
    for (int i = tid; i < K_DIM; i += THREADS) e2s[i] = g_e2[i];
    {
        const float semax = sqrtf(__int_as_float(g_emax_bits));
        for (int i = tid; i < BM; i += THREADS) {
            marg[i] = 0.00390625f * sqrtf(g_xn2[n0 + i]) * semax + 4e-3f;
            runmin[i] = CUDART_INF_F;
            umin[i] = ~0ULL;
        }
    }
    __syncthreads();

    float best[4];
#pragma unroll
    for (int s = 0; s < 4; ++s) best[s] = CUDART_INF_F;

    for (int kt = 0; kt < NKT; ++kt) {
        const int k0 = kt * BN;
        float acc[2][4][4];
#pragma unroll
        for (int mt = 0; mt < 2; ++mt)
#pragma unroll
            for (int nt = 0; nt < 4; ++nt)
#pragma unroll
                for (int j = 0; j < 4; ++j) acc[mt][nt][j] = 0.f;

        __syncthreads();
        stage(sm, 0, k0, xb, emb, tid);
        __syncthreads();

        for (int ch = 0; ch < NCH; ++ch) {
            float* cur = sm + (ch & 1) * BUF_FLOATS;
            if (ch + 1 < NCH)
                stage(sm + ((ch + 1) & 1) * BUF_FLOATS, (ch + 1) * DC, k0, xb, emb, tid);

            const float* AH = cur;
            const float* BH = cur + TILE_FLOATS;
#pragma unroll
            for (int g = 0; g < 4; ++g) {
                const int kkA = g * 8 + tig;
                uint32_t ahi[2][4];
#pragma unroll
                for (int mt = 0; mt < 2; ++mt) {
                    const int M0 = mbw + mt * 16 + gid;
                    ahi[mt][0] = __float_as_uint(AH[kkA * 128 + (M0 ^ sw)]);
                    ahi[mt][1] = __float_as_uint(AH[kkA * 128 + ((M0 + 8) ^ sw)]);
                    ahi[mt][2] = __float_as_uint(AH[(kkA + 4) * 128 + (M0 ^ sw)]);
                    ahi[mt][3] = __float_as_uint(AH[(kkA + 4) * 128 + ((M0 + 8) ^ sw)]);
                }
#pragma unroll
                for (int nt = 0; nt < 4; ++nt) {
                    const int n = nbw + nt * 8 + gid;
                    uint32_t bh[2];
                    bh[0] = __float_as_uint(BH[kkA * 128 + (n ^ sw)]);
                    bh[1] = __float_as_uint(BH[(kkA + 4) * 128 + (n ^ sw)]);
                    mma8(acc[0][nt], ahi[0], bh);
                    mma8(acc[1][nt], ahi[1], bh);
                }
            }
            __syncthreads();
        }

        // scores in place; update running best
#pragma unroll
        for (int mt = 0; mt < 2; ++mt)
#pragma unroll
            for (int nt = 0; nt < 4; ++nt) {
                const int kc = k0 + nbw + nt * 8 + 2 * tig;
                acc[mt][nt][0] = fmaf(-2.f, acc[mt][nt][0], e2s[kc]);
                acc[mt][nt][1] = fmaf(-2.f, acc[mt][nt][1], e2s[kc + 1]);
                acc[mt][nt][2] = fmaf(-2.f, acc[mt][nt][2], e2s[kc]);
                acc[mt][nt][3] = fmaf(-2.f, acc[mt][nt][3], e2s[kc + 1]);
                best[2 * mt] = fminf(best[2 * mt], fminf(acc[mt][nt][0], acc[mt][nt][1]));
                best[2 * mt + 1] = fminf(best[2 * mt + 1], fminf(acc[mt][nt][2], acc[mt][nt][3]));
            }

        // running-min reduce (quad lanes share rows)
#pragma unroll
        for (int s = 0; s < 4; ++s) {
            float v = best[s];
#pragma unroll
            for (int off = 1; off <= 2; off <<= 1)
                v = fminf(v, __shfl_xor_sync(0xFFFFFFFFu, v, off));
            if (tig == 0) {
                int row = mbw + (s >> 1) * 16 + gid + (s & 1) * 8;
                redv[row][wn] = v;
            }
        }
        __syncthreads();
        if (tid < BM)
            runmin[tid] = fminf(fminf(redv[tid][0], redv[tid][1]),
                                fminf(redv[tid][2], redv[tid][3]));
        __syncthreads();

        // candidate scan for this tile (threshold uses running min: superset, safe)
#pragma unroll
        for (int mt = 0; mt < 2; ++mt) {
            const int r0 = mbw + mt * 16 + gid;
            const float t0 = runmin[r0] + marg[r0];
            const float t1 = runmin[r0 + 8] + marg[r0 + 8];
#pragma unroll
            for (int nt = 0; nt < 4; ++nt) {
                const int kc = k0 + nbw + nt * 8 + 2 * tig;
                if (acc[mt][nt][0] <= t0) { int p = atomicAdd(&cand_cnt, 1); if (p < CAP) cand[p] = (r0 << 10) | kc; }
                if (acc[mt][nt][1] <= t0) { int p = atomicAdd(&cand_cnt, 1); if (p < CAP) cand[p] = (r0 << 10) | (kc + 1); }
                if (acc[mt][nt][2] <= t1) { int p = atomicAdd(&cand_cnt, 1); if (p < CAP) cand[p] = ((r0 + 8) << 10) | kc; }
                if (acc[mt][nt][3] <= t1) { int p = atomicAdd(&cand_cnt, 1); if (p < CAP) cand[p] = ((r0 + 8) << 10) | (kc + 1); }
            }
        }
        __syncthreads();
    }

    // exact double-precision re-rank of candidates
    {
        int cnt = cand_cnt;
        if (cnt > CAP) cnt = CAP;
        for (int i = tid; i < cnt; i += THREADS) {
            int c = cand[i];
            int row = c >> 10;
            int k = c & 1023;
            const float* xr = g_xT + (size_t)(n0 + row) * D_DIM;
            const float* er = g_eT + (size_t)k * D_DIM;
            double s0 = 0.0, s1 = 0.0, s2 = 0.0, s3 = 0.0;
#pragma unroll 4
            for (int d = 0; d < D_DIM; d += 4) {
                float4 xv = *(const float4*)(xr + d);
                float4 ev = *(const float4*)(er + d);
                s0 = fma((double)ev.x, (double)ev.x - 2.0 * (double)xv.x, s0);
                s1 = fma((double)ev.y, (double)ev.y - 2.0 * (double)xv.y, s1);
                s2 = fma((double)ev.z, (double)ev.z - 2.0 * (double)xv.z, s2);
                s3 = fma((double)ev.w, (double)ev.w - 2.0 * (double)xv.w, s3);
            }
            double sc = (s0 + s1) + (s2 + s3);
            long long bits = __double_as_longlong(sc);
            unsigned long long u = (unsigned long long)bits;
            u ^= (bits < 0) ? 0xFFFFFFFFFFFFFFFFULL : 0x8000000000000000ULL;
            unsigned long long v = (u & ~1023ULL) | (unsigned long long)k;
            atomicMin(&umin[row], v);
        }
    }
    __syncthreads();
    if (tid < BM) {
        int bi = (int)(umin[tid] & 1023ULL);
        kwin[tid] = bi;
        if (has_idx) idx_out[n0 + tid] = (float)bi;
    }
    __syncthreads();

    // gather nearest code (exact fp32), scatter to (B,D,H,W)
    for (int r = tid; r < D_DIM * BM; r += THREADS) {
        int d = r >> 7;
        int m = r & (BM - 1);
        out[((size_t)b * D_DIM + d) * 1024 + hw0 + m] = emb[(size_t)d * K_DIM + kwin[m]];
    }
}

extern "C" void kernel_launch(void* const* d_in, const int* in_sizes, int n_in,
                              void* d_out, int out_size) {
    const float* x = (const float*)d_in[0];    // (64,256,32,32)
    const float* emb = (const float*)d_in[1];  // (256,1024)
    float* out = (float*)d_out;

    const int n_img = 64 * 256 * 32 * 32;
    const int n_lat = 64 * 32 * 32;
    float* idx_out = nullptr;
    int has_idx = 0;
    if (out_size >= n_img + n_lat) {
        idx_out = out + n_img;
        has_idx = 1;
    }

    cudaFuncSetAttribute(vq_mma_kernel, cudaFuncAttributeMaxDynamicSharedMemorySize, SMEM_DYN);

    e2_kernel<<<4, 256>>>(emb);
    xt_kernel<<<dim3(32, 8, 64), dim3(32, 8)>>>(x);
    et_kernel<<<dim3(32, 8, 1), dim3(32, 8)>>>(emb);
    xn2_kernel<<<65536 / 8, 256>>>();
    vq_mma_kernel<<<512, THREADS, SMEM_DYN>>>(x, emb, out, idx_out, has_idx);
}

// round 8
// speedup vs baseline: 1.1505x; 1.0548x over previous
#include <cuda_runtime.h>
#include <cstdint>
#include <math_constants.h>

// NearestEmbed, filter-then-rerank, split pipeline (R8):
//   1) prep: e2/emax, xT, eT, xn2, init
//   2) vq_mma_kernel: 1-pass tf32 GEMM + margin filter -> global candidate list
//   3) rerank_kernel: exact double dot per candidate (warp per candidate)
//   4) gather_kernel: write out + idx
// score[n,k] = ||e_k||^2 - 2 * x_n . e_k

#define D_DIM 256
#define K_DIM 1024
#define BM 128
#define BN 128
#define DC 32
#define NKT (K_DIM / BN)
#define NCH (D_DIM / DC)
#define THREADS 512
#define CAP 4096                         // per-CTA smem candidate cap
#define GCAP (2 * 1024 * 1024)           // global candidate cap

#define TILE_FLOATS (DC * BM)            // 4096 floats = 16KB
#define BUF_FLOATS (2 * TILE_FLOATS)     // A, B
#define SMEM_DYN (2 * BUF_FLOATS * 4)    // 65536 bytes

#define N_LAT (64 * 1024)

__device__ float g_e2[K_DIM];
__device__ int g_emax_bits;
__device__ float g_xn2[N_LAT];
__device__ float g_xT[(size_t)N_LAT * D_DIM];   // [n][d]
__device__ float g_eT[K_DIM * D_DIM];           // [k][d]
__device__ int g_cand[GCAP];
__device__ int g_cand_cnt;
__device__ unsigned long long g_umin[N_LAT];

__device__ __forceinline__ uint32_t to_tf32(float f) {
    uint32_t r;
    asm("cvt.rna.tf32.f32 %0, %1;" : "=r"(r) : "f"(f));
    return r;
}

__device__ __forceinline__ void mma8(float* c, const uint32_t* a, const uint32_t* b) {
    asm volatile(
        "mma.sync.aligned.m16n8k8.row.col.f32.tf32.tf32.f32 "
        "{%0,%1,%2,%3}, {%4,%5,%6,%7}, {%8,%9}, {%0,%1,%2,%3};"
        : "+f"(c[0]), "+f"(c[1]), "+f"(c[2]), "+f"(c[3])
        : "r"(a[0]), "r"(a[1]), "r"(a[2]), "r"(a[3]), "r"(b[0]), "r"(b[1]));
}

// ---------------- prep kernels ----------------
__global__ void init_kernel() {
    int i = blockIdx.x * blockDim.x + threadIdx.x;
    if (i < N_LAT) g_umin[i] = ~0ULL;
    if (i == 0) g_cand_cnt = 0;
}

__global__ void e2_kernel(const float* __restrict__ emb) {
    int k = blockIdx.x * blockDim.x + threadIdx.x;
    float s = 0.f;
#pragma unroll 8
    for (int d = 0; d < D_DIM; ++d) {
        float v = emb[(size_t)d * K_DIM + k];
        s = fmaf(v, v, s);
    }
    g_e2[k] = s;
    atomicMax(&g_emax_bits, __float_as_int(s));
}

__global__ void xt_kernel(const float* __restrict__ x) {
    __shared__ float t[32][33];
    const int b = blockIdx.z;
    const int d0 = blockIdx.y * 32;
    const int hw0 = blockIdx.x * 32;
    const int tx = threadIdx.x, ty = threadIdx.y;
#pragma unroll
    for (int i = 0; i < 4; ++i)
        t[ty + i * 8][tx] = x[((size_t)b * D_DIM + d0 + ty + i * 8) * 1024 + hw0 + tx];
    __syncthreads();
#pragma unroll
    for (int i = 0; i < 4; ++i) {
        int n = b * 1024 + hw0 + ty + i * 8;
        g_xT[(size_t)n * D_DIM + d0 + tx] = t[tx][ty + i * 8];
    }
}

__global__ void et_kernel(const float* __restrict__ emb) {
    __shared__ float t[32][33];
    const int d0 = blockIdx.y * 32;
    const int k0 = blockIdx.x * 32;
    const int tx = threadIdx.x, ty = threadIdx.y;
#pragma unroll
    for (int i = 0; i < 4; ++i)
        t[ty + i * 8][tx] = emb[(size_t)(d0 + ty + i * 8) * K_DIM + k0 + tx];
    __syncthreads();
#pragma unroll
    for (int i = 0; i < 4; ++i)
        g_eT[(size_t)(k0 + ty + i * 8) * D_DIM + d0 + tx] = t[tx][ty + i * 8];
}

__global__ void xn2_kernel() {
    int w = (blockIdx.x * blockDim.x + threadIdx.x) >> 5;
    int lane = threadIdx.x & 31;
    const float* r = g_xT + (size_t)w * D_DIM;
    float s = 0.f;
#pragma unroll
    for (int d = lane; d < D_DIM; d += 32) {
        float v = r[d];
        s = fmaf(v, v, s);
    }
#pragma unroll
    for (int off = 16; off > 0; off >>= 1) s += __shfl_xor_sync(0xFFFFFFFFu, s, off);
    if (lane == 0) g_xn2[w] = s;
}

// ---------------- GEMM + filter ----------------
__device__ __forceinline__ void stage(float* __restrict__ buf, int dt, int k0,
                                      const float* __restrict__ xb,
                                      const float* __restrict__ emb, int tid) {
#pragma unroll
    for (int i = 0; i < 2; ++i) {
        int f = tid + i * THREADS;
        int kk = f >> 5;
        int q = f & 31;
        int w = kk * 128 + ((4 * q) ^ ((kk & 3) << 3));
        float4 va = *(const float4*)(xb + (size_t)(dt + kk) * 1024 + 4 * q);
        float4 vb = *(const float4*)(emb + (size_t)(dt + kk) * K_DIM + k0 + 4 * q);
        uint4 ha = make_uint4(to_tf32(va.x), to_tf32(va.y), to_tf32(va.z), to_tf32(va.w));
        uint4 hb = make_uint4(to_tf32(vb.x), to_tf32(vb.y), to_tf32(vb.z), to_tf32(vb.w));
        *(uint4*)(buf + w) = ha;
        *(uint4*)(buf + TILE_FLOATS + w) = hb;
    }
}

__global__ __launch_bounds__(THREADS, 1)
void vq_mma_kernel(const float* __restrict__ x, const float* __restrict__ emb) {
    extern __shared__ float sm[];
    __shared__ float e2s[K_DIM];
    __shared__ float redv[BM][4];
    __shared__ float runmin[BM];
    __shared__ float marg[BM];
    __shared__ int cand[CAP];
    __shared__ int cand_cnt;
    __shared__ int flush_base;

    const int tid = threadIdx.x;
    const int wid = tid >> 5;
    const int lane = tid & 31;
    const int gid = lane >> 2;
    const int tig = lane & 3;
    const int wm = wid >> 2;
    const int wn = wid & 3;
    const int mbw = wm * 32;
    const int nbw = wn * 32;
    const int sw = tig << 3;

    const int n0 = blockIdx.x * BM;
    const int b = n0 >> 10;
    const int hw0 = n0 & 1023;
    const float* xb = x + (size_t)b * D_DIM * 1024 + hw0;

    if (tid == 0) cand_cnt = 0;
    for (int i = tid; i < K_DIM; i += THREADS) e2s[i] = g_e2[i];
    {
        const float semax = sqrtf(__int_as_float(g_emax_bits));
        for (int i = tid; i < BM; i += THREADS) {
            marg[i] = 0.00390625f * sqrtf(g_xn2[n0 + i]) * semax + 4e-3f;
            runmin[i] = CUDART_INF_F;
        }
    }
    __syncthreads();

    float best[4];
#pragma unroll
    for (int s = 0; s < 4; ++s) best[s] = CUDART_INF_F;

    for (int kt = 0; kt < NKT; ++kt) {
        const int k0 = kt * BN;
        float acc[2][4][4];
#pragma unroll
        for (int mt = 0; mt < 2; ++mt)
#pragma unroll
            for (int nt = 0; nt < 4; ++nt)
#pragma unroll
                for (int j = 0; j < 4; ++j) acc[mt][nt][j] = 0.f;

        __syncthreads();
        stage(sm, 0, k0, xb, emb, tid);
        __syncthreads();

        for (int ch = 0; ch < NCH; ++ch) {
            float* cur = sm + (ch & 1) * BUF_FLOATS;
            if (ch + 1 < NCH)
                stage(sm + ((ch + 1) & 1) * BUF_FLOATS, (ch + 1) * DC, k0, xb, emb, tid);

            const float* AH = cur;
            const float* BH = cur + TILE_FLOATS;
#pragma unroll
            for (int g = 0; g < 4; ++g) {
                const int kkA = g * 8 + tig;
                uint32_t ahi[2][4];
#pragma unroll
                for (int mt = 0; mt < 2; ++mt) {
                    const int M0 = mbw + mt * 16 + gid;
                    ahi[mt][0] = __float_as_uint(AH[kkA * 128 + (M0 ^ sw)]);
                    ahi[mt][1] = __float_as_uint(AH[kkA * 128 + ((M0 + 8) ^ sw)]);
                    ahi[mt][2] = __float_as_uint(AH[(kkA + 4) * 128 + (M0 ^ sw)]);
                    ahi[mt][3] = __float_as_uint(AH[(kkA + 4) * 128 + ((M0 + 8) ^ sw)]);
                }
#pragma unroll
                for (int nt = 0; nt < 4; ++nt) {
                    const int n = nbw + nt * 8 + gid;
                    uint32_t bh[2];
                    bh[0] = __float_as_uint(BH[kkA * 128 + (n ^ sw)]);
                    bh[1] = __float_as_uint(BH[(kkA + 4) * 128 + (n ^ sw)]);
                    mma8(acc[0][nt], ahi[0], bh);
                    mma8(acc[1][nt], ahi[1], bh);
                }
            }
            __syncthreads();
        }

        // approx scores; update running best
#pragma unroll
        for (int mt = 0; mt < 2; ++mt)
#pragma unroll
            for (int nt = 0; nt < 4; ++nt) {
                const int kc = k0 + nbw + nt * 8 + 2 * tig;
                acc[mt][nt][0] = fmaf(-2.f, acc[mt][nt][0], e2s[kc]);
                acc[mt][nt][1] = fmaf(-2.f, acc[mt][nt][1], e2s[kc + 1]);
                acc[mt][nt][2] = fmaf(-2.f, acc[mt][nt][2], e2s[kc]);
                acc[mt][nt][3] = fmaf(-2.f, acc[mt][nt][3], e2s[kc + 1]);
                best[2 * mt] = fminf(best[2 * mt], fminf(acc[mt][nt][0], acc[mt][nt][1]));
                best[2 * mt + 1] = fminf(best[2 * mt + 1], fminf(acc[mt][nt][2], acc[mt][nt][3]));
            }

        // running-min reduce (quad lanes share rows)
#pragma unroll
        for (int s = 0; s < 4; ++s) {
            float v = best[s];
#pragma unroll
            for (int off = 1; off <= 2; off <<= 1)
                v = fminf(v, __shfl_xor_sync(0xFFFFFFFFu, v, off));
            if (tig == 0) {
                int row = mbw + (s >> 1) * 16 + gid + (s & 1) * 8;
                redv[row][wn] = v;
            }
        }
        __syncthreads();
        if (tid < BM)
            runmin[tid] = fminf(fminf(redv[tid][0], redv[tid][1]),
                                fminf(redv[tid][2], redv[tid][3]));
        __syncthreads();

        // candidate scan (running min + margin -> superset of true argmin, safe)
#pragma unroll
        for (int mt = 0; mt < 2; ++mt) {
            const int r0 = mbw + mt * 16 + gid;
            const float t0 = runmin[r0] + marg[r0];
            const float t1 = runmin[r0 + 8] + marg[r0 + 8];
#pragma unroll
            for (int nt = 0; nt < 4; ++nt) {
                const int kc = k0 + nbw + nt * 8 + 2 * tig;
                if (acc[mt][nt][0] <= t0) { int p = atomicAdd(&cand_cnt, 1); if (p < CAP) cand[p] = ((n0 + r0) << 10) | kc; }
                if (acc[mt][nt][1] <= t0) { int p = atomicAdd(&cand_cnt, 1); if (p < CAP) cand[p] = ((n0 + r0) << 10) | (kc + 1); }
                if (acc[mt][nt][2] <= t1) { int p = atomicAdd(&cand_cnt, 1); if (p < CAP) cand[p] = ((n0 + r0 + 8) << 10) | kc; }
                if (acc[mt][nt][3] <= t1) { int p = atomicAdd(&cand_cnt, 1); if (p < CAP) cand[p] = ((n0 + r0 + 8) << 10) | (kc + 1); }
            }
        }
        __syncthreads();
    }

    // flush candidates to global list
    int cnt = cand_cnt;
    if (cnt > CAP) cnt = CAP;
    if (tid == 0) flush_base = atomicAdd(&g_cand_cnt, cnt);
    __syncthreads();
    int base = flush_base;
    for (int i = tid; i < cnt; i += THREADS)
        if (base + i < GCAP) g_cand[base + i] = cand[i];
}

// ---------------- exact re-rank (warp per candidate) ----------------
__global__ void rerank_kernel() {
    const int nwarp = (gridDim.x * blockDim.x) >> 5;
    const int w = (blockIdx.x * blockDim.x + threadIdx.x) >> 5;
    const int lane = threadIdx.x & 31;
    int cnt = g_cand_cnt;
    if (cnt > GCAP) cnt = GCAP;

    for (int i = w; i < cnt; i += nwarp) {
        int c = g_cand[i];
        int n = c >> 10;
        int k = c & 1023;
        const float4* xr = (const float4*)(g_xT + (size_t)n * D_DIM);
        const float4* er = (const float4*)(g_eT + (size_t)k * D_DIM);
        double s = 0.0;
#pragma unroll
        for (int j = 0; j < 2; ++j) {
            float4 xv = xr[lane + j * 32];
            float4 ev = er[lane + j * 32];
            s = fma((double)ev.x, (double)ev.x - 2.0 * (double)xv.x, s);
            s = fma((double)ev.y, (double)ev.y - 2.0 * (double)xv.y, s);
            s = fma((double)ev.z, (double)ev.z - 2.0 * (double)xv.z, s);
            s = fma((double)ev.w, (double)ev.w - 2.0 * (double)xv.w, s);
        }
#pragma unroll
        for (int off = 16; off > 0; off >>= 1)
            s += __shfl_xor_sync(0xFFFFFFFFu, s, off);
        if (lane == 0) {
            long long bits = __double_as_longlong(s);
            unsigned long long u = (unsigned long long)bits;
            u ^= (bits < 0) ? 0xFFFFFFFFFFFFFFFFULL : 0x8000000000000000ULL;
            unsigned long long v = (u & ~1023ULL) | (unsigned long long)k;
            atomicMin(&g_umin[n], v);
        }
    }
}

// ---------------- gather / output ----------------
__global__ void gather_kernel(const float* __restrict__ emb, float* __restrict__ out,
                              float* __restrict__ idx_out, int has_idx) {
    __shared__ int kwin[BM];
    const int tid = threadIdx.x;
    const int n0 = blockIdx.x * BM;
    const int b = n0 >> 10;
    const int hw0 = n0 & 1023;
    if (tid < BM) {
        int k = (int)(g_umin[n0 + tid] & 1023ULL);
        kwin[tid] = k;
        if (has_idx) idx_out[n0 + tid] = (float)k;
    }
    __syncthreads();
    for (int r = tid; r < D_DIM * BM; r += 256) {
        int d = r >> 7;
        int m = r & (BM - 1);
        out[((size_t)b * D_DIM + d) * 1024 + hw0 + m] = emb[(size_t)d * K_DIM + kwin[m]];
    }
}

extern "C" void kernel_launch(void* const* d_in, const int* in_sizes, int n_in,
                              void* d_out, int out_size) {
    const float* x = (const float*)d_in[0];    // (64,256,32,32)
    const float* emb = (const float*)d_in[1];  // (256,1024)
    float* out = (float*)d_out;

    const int n_img = 64 * 256 * 32 * 32;
    const int n_lat = 64 * 32 * 32;
    float* idx_out = nullptr;
    int has_idx = 0;
    if (out_size >= n_img + n_lat) {
        idx_out = out + n_img;
        has_idx = 1;
    }

    cudaFuncSetAttribute(vq_mma_kernel, cudaFuncAttributeMaxDynamicSharedMemorySize, SMEM_DYN);

    init_kernel<<<N_LAT / 256, 256>>>();
    e2_kernel<<<4, 256>>>(emb);
    xt_kernel<<<dim3(32, 8, 64), dim3(32, 8)>>>(x);
    et_kernel<<<dim3(32, 8, 1), dim3(32, 8)>>>(emb);
    xn2_kernel<<<N_LAT / 8, 256>>>();
    vq_mma_kernel<<<512, THREADS, SMEM_DYN>>>(x, emb);
    rerank_kernel<<<1024, 256>>>();
    gather_kernel<<<512, 256>>>(emb, out, idx_out, has_idx);
}

// round 9
// speedup vs baseline: 1.7856x; 1.5520x over previous
#include <cuda_runtime.h>
#include <cstdint>
#include <math_constants.h>

// NearestEmbed via mma.sync tf32 (3xTF32 split) + fused argmin epilogue.
// R9 = R4 (best GEMM) with cp.async staging: no LDG->STS register stall.
// score[n,k] = ||e_k||^2 - 2 * x_n . e_k
// dot = xhi.ehi + xhi.elo + xlo.ehi  (tf32 split, fp32 accumulate)

#define D_DIM 256
#define K_DIM 1024
#define BM 128
#define BN 128
#define DC 32
#define NKT (K_DIM / BN)
#define NCH (D_DIM / DC)
#define THREADS 512

#define TILE_FLOATS (DC * BM)            // 4096 floats
#define TILE_BYTES (TILE_FLOATS * 4)     // 16384
#define BUF_FLOATS (4 * TILE_FLOATS)     // AH, AL, BH, BL
#define BUF_BYTES (4 * TILE_BYTES)       // 65536
#define SMEM_DYN (2 * BUF_BYTES)         // 131072

__device__ float g_e2[K_DIM];
__device__ float g_xhi[64 * 256 * 1024];
__device__ float g_xlo[64 * 256 * 1024];
__device__ float g_ehi[D_DIM * K_DIM];
__device__ float g_elo[D_DIM * K_DIM];

__device__ __forceinline__ uint32_t to_tf32(float f) {
    uint32_t r;
    asm("cvt.rna.tf32.f32 %0, %1;" : "=r"(r) : "f"(f));
    return r;
}

__device__ __forceinline__ uint32_t smem_u32(const void* p) {
    uint32_t a;
    asm("{ .reg .u64 t; cvta.to.shared.u64 t, %1; cvt.u32.u64 %0, t; }" : "=r"(a) : "l"(p));
    return a;
}

__device__ __forceinline__ void cp16(uint32_t dst, const void* src) {
    asm volatile("cp.async.cg.shared.global [%0], [%1], 16;" :: "r"(dst), "l"(src) : "memory");
}
#define CP_COMMIT() asm volatile("cp.async.commit_group;" ::: "memory")
#define CP_WAIT(N)  asm volatile("cp.async.wait_group %0;" :: "n"(N) : "memory")

__device__ __forceinline__ void mma8(float* c, const uint32_t* a, const uint32_t* b) {
    asm volatile(
        "mma.sync.aligned.m16n8k8.row.col.f32.tf32.tf32.f32 "
        "{%0,%1,%2,%3}, {%4,%5,%6,%7}, {%8,%9}, {%0,%1,%2,%3};"
        : "+f"(c[0]), "+f"(c[1]), "+f"(c[2]), "+f"(c[3])
        : "r"(a[0]), "r"(a[1]), "r"(a[2]), "r"(a[3]), "r"(b[0]), "r"(b[1]));
}

// ---------------- prep kernels ----------------
__global__ void e2_kernel(const float* __restrict__ emb) {
    int k = blockIdx.x * blockDim.x + threadIdx.x;
    float s = 0.f;
#pragma unroll 8
    for (int d = 0; d < D_DIM; ++d) {
        float v = emb[(size_t)d * K_DIM + k];
        s = fmaf(v, v, s);
    }
    g_e2[k] = s;
}

__global__ void cvt_kernel(const float* __restrict__ src, float* __restrict__ dhi,
                           float* __restrict__ dlo) {
    size_t i = ((size_t)blockIdx.x * blockDim.x + threadIdx.x) * 4;
    float4 v = *(const float4*)(src + i);
    float4 h, l;
    h.x = __uint_as_float(to_tf32(v.x)); l.x = __uint_as_float(to_tf32(v.x - h.x));
    h.y = __uint_as_float(to_tf32(v.y)); l.y = __uint_as_float(to_tf32(v.y - h.y));
    h.z = __uint_as_float(to_tf32(v.z)); l.z = __uint_as_float(to_tf32(v.z - h.z));
    h.w = __uint_as_float(to_tf32(v.w)); l.w = __uint_as_float(to_tf32(v.w - h.w));
    *(float4*)(dhi + i) = h;
    *(float4*)(dlo + i) = l;
}

// ---------------- main kernel ----------------
// cp.async staging: 8 LDGSTS of 16B per thread per chunk, no register round-trip.
__device__ __forceinline__ void stage_async(uint32_t smb, int bufsel, int dt, int k0,
                                            size_t xoff, int tid) {
    const float* xh = g_xhi + xoff;
    const float* xl = g_xlo + xoff;
    const uint32_t base = smb + bufsel * BUF_BYTES;
#pragma unroll
    for (int i = 0; i < 2; ++i) {
        int f = tid + i * THREADS;
        int kk = f >> 5;
        int q = f & 31;
        uint32_t wb = (uint32_t)(kk * 128 + ((4 * q) ^ ((kk & 3) << 3))) * 4u;
        size_t arow = (size_t)(dt + kk) * 1024 + 4 * q;
        size_t brow = (size_t)(dt + kk) * K_DIM + k0 + 4 * q;
        cp16(base + wb, xh + arow);
        cp16(base + TILE_BYTES + wb, xl + arow);
        cp16(base + 2 * TILE_BYTES + wb, g_ehi + brow);
        cp16(base + 3 * TILE_BYTES + wb, g_elo + brow);
    }
}

__global__ __launch_bounds__(THREADS, 1)
void vq_mma_kernel(const float* __restrict__ emb, float* __restrict__ out,
                   float* __restrict__ idx_out, int has_idx) {
    extern __shared__ float sm[];
    __shared__ float e2s[K_DIM];
    __shared__ float redv[BM][4];
    __shared__ int redi[BM][4];
    __shared__ int idx_s[BM];

    const int tid = threadIdx.x;
    const int wid = tid >> 5;
    const int lane = tid & 31;
    const int gid = lane >> 2;
    const int tig = lane & 3;
    const int wm = wid >> 2;
    const int wn = wid & 3;
    const int mbw = wm * 32;
    const int nbw = wn * 32;
    const int sw = tig << 3;
    const uint32_t smb = smem_u32(sm);

    const int n0 = blockIdx.x * BM;
    const int b = n0 >> 10;
    const int hw0 = n0 & 1023;
    const size_t xoff = (size_t)b * D_DIM * 1024 + hw0;

    for (int i = tid; i < K_DIM; i += THREADS) e2s[i] = g_e2[i];

    float best[4];
    int bidx[4];
#pragma unroll
    for (int s = 0; s < 4; ++s) { best[s] = CUDART_INF_F; bidx[s] = 0; }

    for (int kt = 0; kt < NKT; ++kt) {
        const int k0 = kt * BN;
        float acc[2][4][4];
#pragma unroll
        for (int mt = 0; mt < 2; ++mt)
#pragma unroll
            for (int nt = 0; nt < 4; ++nt)
#pragma unroll
                for (int j = 0; j < 4; ++j) acc[mt][nt][j] = 0.f;

        stage_async(smb, 0, 0, k0, xoff, tid);
        CP_COMMIT();

        for (int ch = 0; ch < NCH; ++ch) {
            if (ch + 1 < NCH) {
                stage_async(smb, (ch + 1) & 1, (ch + 1) * DC, k0, xoff, tid);
                CP_COMMIT();
                CP_WAIT(1);   // current chunk's group complete
            } else {
                CP_WAIT(0);
            }
            __syncthreads();

            const float* cur = sm + (ch & 1) * BUF_FLOATS;
            const float* AH = cur;
            const float* AL = cur + TILE_FLOATS;
            const float* BH = cur + 2 * TILE_FLOATS;
            const float* BL = cur + 3 * TILE_FLOATS;

#pragma unroll
            for (int g = 0; g < 4; ++g) {
                const int kkA = g * 8 + tig;
                uint32_t ahi[2][4], alo[2][4];
#pragma unroll
                for (int mt = 0; mt < 2; ++mt) {
                    const int M0 = mbw + mt * 16 + gid;
                    int w0 = kkA * 128 + (M0 ^ sw);
                    int w1 = kkA * 128 + ((M0 + 8) ^ sw);
                    int w2 = (kkA + 4) * 128 + (M0 ^ sw);
                    int w3 = (kkA + 4) * 128 + ((M0 + 8) ^ sw);
                    ahi[mt][0] = __float_as_uint(AH[w0]);
                    ahi[mt][1] = __float_as_uint(AH[w1]);
                    ahi[mt][2] = __float_as_uint(AH[w2]);
                    ahi[mt][3] = __float_as_uint(AH[w3]);
                    alo[mt][0] = __float_as_uint(AL[w0]);
                    alo[mt][1] = __float_as_uint(AL[w1]);
                    alo[mt][2] = __float_as_uint(AL[w2]);
                    alo[mt][3] = __float_as_uint(AL[w3]);
                }
#pragma unroll
                for (int nt = 0; nt < 4; ++nt) {
                    const int n = nbw + nt * 8 + gid;
                    int w0 = kkA * 128 + (n ^ sw);
                    int w1 = (kkA + 4) * 128 + (n ^ sw);
                    uint32_t bh[2], bl[2];
                    bh[0] = __float_as_uint(BH[w0]);
                    bh[1] = __float_as_uint(BH[w1]);
                    bl[0] = __float_as_uint(BL[w0]);
                    bl[1] = __float_as_uint(BL[w1]);
                    mma8(acc[0][nt], ahi[0], bh);
                    mma8(acc[0][nt], ahi[0], bl);
                    mma8(acc[0][nt], alo[0], bh);
                    mma8(acc[1][nt], ahi[1], bh);
                    mma8(acc[1][nt], ahi[1], bl);
                    mma8(acc[1][nt], alo[1], bh);
                }
            }
            __syncthreads();
        }

        // fused argmin epilogue for this 128-code tile
#pragma unroll
        for (int mt = 0; mt < 2; ++mt) {
#pragma unroll
            for (int nt = 0; nt < 4; ++nt) {
                const int kc = k0 + nbw + nt * 8 + 2 * tig;
                const float e20 = e2s[kc], e21 = e2s[kc + 1];
                float s0 = fmaf(-2.f, acc[mt][nt][0], e20);
                float s1 = fmaf(-2.f, acc[mt][nt][1], e21);
                float s2 = fmaf(-2.f, acc[mt][nt][2], e20);
                float s3 = fmaf(-2.f, acc[mt][nt][3], e21);
                if (s0 < best[2 * mt]) { best[2 * mt] = s0; bidx[2 * mt] = kc; }
                if (s1 < best[2 * mt]) { best[2 * mt] = s1; bidx[2 * mt] = kc + 1; }
                if (s2 < best[2 * mt + 1]) { best[2 * mt + 1] = s2; bidx[2 * mt + 1] = kc; }
                if (s3 < best[2 * mt + 1]) { best[2 * mt + 1] = s3; bidx[2 * mt + 1] = kc + 1; }
            }
        }
    }

    // reduce across the 4 lanes of each quad (same rows, different cols)
#pragma unroll
    for (int s = 0; s < 4; ++s) {
        float v = best[s];
        int ix = bidx[s];
#pragma unroll
        for (int off = 1; off <= 2; off <<= 1) {
            float v2 = __shfl_xor_sync(0xFFFFFFFFu, v, off);
            int i2 = __shfl_xor_sync(0xFFFFFFFFu, ix, off);
            if (v2 < v || (v2 == v && i2 < ix)) { v = v2; ix = i2; }
        }
        if (tig == 0) {
            int row = mbw + (s >> 1) * 16 + gid + (s & 1) * 8;
            redv[row][wn] = v;
            redi[row][wn] = ix;
        }
    }
    __syncthreads();
    if (tid < BM) {
        float bv = redv[tid][0];
        int bi = redi[tid][0];
#pragma unroll
        for (int t = 1; t < 4; ++t) {
            float v = redv[tid][t];
            int id = redi[tid][t];
            if (v < bv || (v == bv && id < bi)) { bv = v; bi = id; }
        }
        idx_s[tid] = bi;
        if (has_idx) idx_out[n0 + tid] = (float)bi;
    }
    __syncthreads();

    // gather nearest code (exact fp32), scatter to (B,D,H,W)
    for (int r = tid; r < D_DIM * BM; r += THREADS) {
        int d = r >> 7;
        int m = r & (BM - 1);
        out[((size_t)b * D_DIM + d) * 1024 + hw0 + m] = emb[(size_t)d * K_DIM + idx_s[m]];
    }
}

extern "C" void kernel_launch(void* const* d_in, const int* in_sizes, int n_in,
                              void* d_out, int out_size) {
    const float* x = (const float*)d_in[0];    // (64,256,32,32)
    const float* emb = (const float*)d_in[1];  // (256,1024)
    float* out = (float*)d_out;

    const int n_img = 64 * 256 * 32 * 32;
    const int n_lat = 64 * 32 * 32;
    float* idx_out = nullptr;
    int has_idx = 0;
    if (out_size >= n_img + n_lat) {
        idx_out = out + n_img;
        has_idx = 1;
    }

    cudaFuncSetAttribute(vq_mma_kernel, cudaFuncAttributeMaxDynamicSharedMemorySize, SMEM_DYN);

    float* xhi; cudaGetSymbolAddress((void**)&xhi, g_xhi);
    float* xlo; cudaGetSymbolAddress((void**)&xlo, g_xlo);
    float* ehi; cudaGetSymbolAddress((void**)&ehi, g_ehi);
    float* elo; cudaGetSymbolAddress((void**)&elo, g_elo);

    e2_kernel<<<4, 256>>>(emb);
    cvt_kernel<<<n_img / 1024, 256>>>(x, xhi, xlo);
    cvt_kernel<<<(D_DIM * K_DIM) / 1024, 256>>>(emb, ehi, elo);
    vq_mma_kernel<<<512, THREADS, SMEM_DYN>>>(emb, out, idx_out, has_idx);
}

// round 10
// speedup vs baseline: 1.7896x; 1.0022x over previous
#include <cuda_runtime.h>
#include <cstdint>
#include <math_constants.h>

// NearestEmbed via mma.sync tf32 (3xTF32 split) + fused argmin epilogue.
// R10 = R9 (cp.async staging) + pass-major MMA ordering with B-register reuse:
//   accumulator reuse distance 8 (was 1), no extra LDS.
// score[n,k] = ||e_k||^2 - 2 * x_n . e_k
// dot = xhi.ehi + xhi.elo + xlo.ehi  (tf32 split, fp32 accumulate)

#define D_DIM 256
#define K_DIM 1024
#define BM 128
#define BN 128
#define DC 32
#define NKT (K_DIM / BN)
#define NCH (D_DIM / DC)
#define THREADS 512

#define TILE_FLOATS (DC * BM)            // 4096 floats
#define TILE_BYTES (TILE_FLOATS * 4)     // 16384
#define BUF_FLOATS (4 * TILE_FLOATS)     // AH, AL, BH, BL
#define BUF_BYTES (4 * TILE_BYTES)       // 65536
#define SMEM_DYN (2 * BUF_BYTES)         // 131072

__device__ float g_e2[K_DIM];
__device__ float g_xhi[64 * 256 * 1024];
__device__ float g_xlo[64 * 256 * 1024];
__device__ float g_ehi[D_DIM * K_DIM];
__device__ float g_elo[D_DIM * K_DIM];

__device__ __forceinline__ uint32_t to_tf32(float f) {
    uint32_t r;
    asm("cvt.rna.tf32.f32 %0, %1;" : "=r"(r) : "f"(f));
    return r;
}

__device__ __forceinline__ uint32_t smem_u32(const void* p) {
    uint32_t a;
    asm("{ .reg .u64 t; cvta.to.shared.u64 t, %1; cvt.u32.u64 %0, t; }" : "=r"(a) : "l"(p));
    return a;
}

__device__ __forceinline__ void cp16(uint32_t dst, const void* src) {
    asm volatile("cp.async.cg.shared.global [%0], [%1], 16;" :: "r"(dst), "l"(src) : "memory");
}
#define CP_COMMIT() asm volatile("cp.async.commit_group;" ::: "memory")
#define CP_WAIT(N)  asm volatile("cp.async.wait_group %0;" :: "n"(N) : "memory")

__device__ __forceinline__ void mma8(float* c, const uint32_t* a, const uint32_t* b) {
    asm volatile(
        "mma.sync.aligned.m16n8k8.row.col.f32.tf32.tf32.f32 "
        "{%0,%1,%2,%3}, {%4,%5,%6,%7}, {%8,%9}, {%0,%1,%2,%3};"
        : "+f"(c[0]), "+f"(c[1]), "+f"(c[2]), "+f"(c[3])
        : "r"(a[0]), "r"(a[1]), "r"(a[2]), "r"(a[3]), "r"(b[0]), "r"(b[1]));
}

// ---------------- prep kernels ----------------
__global__ void e2_kernel(const float* __restrict__ emb) {
    int k = blockIdx.x * blockDim.x + threadIdx.x;
    float s = 0.f;
#pragma unroll 8
    for (int d = 0; d < D_DIM; ++d) {
        float v = emb[(size_t)d * K_DIM + k];
        s = fmaf(v, v, s);
    }
    g_e2[k] = s;
}

__global__ void cvt_kernel(const float* __restrict__ src, float* __restrict__ dhi,
                           float* __restrict__ dlo) {
    size_t i = ((size_t)blockIdx.x * blockDim.x + threadIdx.x) * 4;
    float4 v = *(const float4*)(src + i);
    float4 h, l;
    h.x = __uint_as_float(to_tf32(v.x)); l.x = __uint_as_float(to_tf32(v.x - h.x));
    h.y = __uint_as_float(to_tf32(v.y)); l.y = __uint_as_float(to_tf32(v.y - h.y));
    h.z = __uint_as_float(to_tf32(v.z)); l.z = __uint_as_float(to_tf32(v.z - h.z));
    h.w = __uint_as_float(to_tf32(v.w)); l.w = __uint_as_float(to_tf32(v.w - h.w));
    *(float4*)(dhi + i) = h;
    *(float4*)(dlo + i) = l;
}

// ---------------- main kernel ----------------
__device__ __forceinline__ void stage_async(uint32_t smb, int bufsel, int dt, int k0,
                                            size_t xoff, int tid) {
    const float* xh = g_xhi + xoff;
    const float* xl = g_xlo + xoff;
    const uint32_t base = smb + bufsel * BUF_BYTES;
#pragma unroll
    for (int i = 0; i < 2; ++i) {
        int f = tid + i * THREADS;
        int kk = f >> 5;
        int q = f & 31;
        uint32_t wb = (uint32_t)(kk * 128 + ((4 * q) ^ ((kk & 3) << 3))) * 4u;
        size_t arow = (size_t)(dt + kk) * 1024 + 4 * q;
        size_t brow = (size_t)(dt + kk) * K_DIM + k0 + 4 * q;
        cp16(base + wb, xh + arow);
        cp16(base + TILE_BYTES + wb, xl + arow);
        cp16(base + 2 * TILE_BYTES + wb, g_ehi + brow);
        cp16(base + 3 * TILE_BYTES + wb, g_elo + brow);
    }
}

__global__ __launch_bounds__(THREADS, 1)
void vq_mma_kernel(const float* __restrict__ emb, float* __restrict__ out,
                   float* __restrict__ idx_out, int has_idx) {
    extern __shared__ float sm[];
    __shared__ float e2s[K_DIM];
    __shared__ float redv[BM][4];
    __shared__ int redi[BM][4];
    __shared__ int idx_s[BM];

    const int tid = threadIdx.x;
    const int wid = tid >> 5;
    const int lane = tid & 31;
    const int gid = lane >> 2;
    const int tig = lane & 3;
    const int wm = wid >> 2;
    const int wn = wid & 3;
    const int mbw = wm * 32;
    const int nbw = wn * 32;
    const int sw = tig << 3;
    const uint32_t smb = smem_u32(sm);

    const int n0 = blockIdx.x * BM;
    const int b = n0 >> 10;
    const int hw0 = n0 & 1023;
    const size_t xoff = (size_t)b * D_DIM * 1024 + hw0;

    for (int i = tid; i < K_DIM; i += THREADS) e2s[i] = g_e2[i];

    float best[4];
    int bidx[4];
#pragma unroll
    for (int s = 0; s < 4; ++s) { best[s] = CUDART_INF_F; bidx[s] = 0; }

    for (int kt = 0; kt < NKT; ++kt) {
        const int k0 = kt * BN;
        float acc[2][4][4];
#pragma unroll
        for (int mt = 0; mt < 2; ++mt)
#pragma unroll
            for (int nt = 0; nt < 4; ++nt)
#pragma unroll
                for (int j = 0; j < 4; ++j) acc[mt][nt][j] = 0.f;

        stage_async(smb, 0, 0, k0, xoff, tid);
        CP_COMMIT();

        for (int ch = 0; ch < NCH; ++ch) {
            if (ch + 1 < NCH) {
                stage_async(smb, (ch + 1) & 1, (ch + 1) * DC, k0, xoff, tid);
                CP_COMMIT();
                CP_WAIT(1);
            } else {
                CP_WAIT(0);
            }
            __syncthreads();

            const float* cur = sm + (ch & 1) * BUF_FLOATS;
            const float* AH = cur;
            const float* AL = cur + TILE_FLOATS;
            const float* BH = cur + 2 * TILE_FLOATS;
            const float* BL = cur + 3 * TILE_FLOATS;

#pragma unroll
            for (int g = 0; g < 4; ++g) {
                const int kkA = g * 8 + tig;
                uint32_t ahi[2][4], alo[2][4], bh[4][2];
#pragma unroll
                for (int mt = 0; mt < 2; ++mt) {
                    const int M0 = mbw + mt * 16 + gid;
                    int w0 = kkA * 128 + (M0 ^ sw);
                    int w1 = kkA * 128 + ((M0 + 8) ^ sw);
                    int w2 = (kkA + 4) * 128 + (M0 ^ sw);
                    int w3 = (kkA + 4) * 128 + ((M0 + 8) ^ sw);
                    ahi[mt][0] = __float_as_uint(AH[w0]);
                    ahi[mt][1] = __float_as_uint(AH[w1]);
                    ahi[mt][2] = __float_as_uint(AH[w2]);
                    ahi[mt][3] = __float_as_uint(AH[w3]);
                    alo[mt][0] = __float_as_uint(AL[w0]);
                    alo[mt][1] = __float_as_uint(AL[w1]);
                    alo[mt][2] = __float_as_uint(AL[w2]);
                    alo[mt][3] = __float_as_uint(AL[w3]);
                }
                // pass 0: hi . bh  (load bh, keep in regs)
#pragma unroll
                for (int nt = 0; nt < 4; ++nt) {
                    const int n = nbw + nt * 8 + gid;
                    bh[nt][0] = __float_as_uint(BH[kkA * 128 + (n ^ sw)]);
                    bh[nt][1] = __float_as_uint(BH[(kkA + 4) * 128 + (n ^ sw)]);
                    mma8(acc[0][nt], ahi[0], bh[nt]);
                    mma8(acc[1][nt], ahi[1], bh[nt]);
                }
                // pass 1: hi . bl
#pragma unroll
                for (int nt = 0; nt < 4; ++nt) {
                    const int n = nbw + nt * 8 + gid;
                    uint32_t bl[2];
                    bl[0] = __float_as_uint(BL[kkA * 128 + (n ^ sw)]);
                    bl[1] = __float_as_uint(BL[(kkA + 4) * 128 + (n ^ sw)]);
                    mma8(acc[0][nt], ahi[0], bl);
                    mma8(acc[1][nt], ahi[1], bl);
                }
                // pass 2: lo . bh  (reuse bh registers, no LDS)
#pragma unroll
                for (int nt = 0; nt < 4; ++nt) {
                    mma8(acc[0][nt], alo[0], bh[nt]);
                    mma8(acc[1][nt], alo[1], bh[nt]);
                }
            }
            __syncthreads();
        }

        // fused argmin epilogue for this 128-code tile
#pragma unroll
        for (int mt = 0; mt < 2; ++mt) {
#pragma unroll
            for (int nt = 0; nt < 4; ++nt) {
                const int kc = k0 + nbw + nt * 8 + 2 * tig;
                const float e20 = e2s[kc], e21 = e2s[kc + 1];
                float s0 = fmaf(-2.f, acc[mt][nt][0], e20);
                float s1 = fmaf(-2.f, acc[mt][nt][1], e21);
                float s2 = fmaf(-2.f, acc[mt][nt][2], e20);
                float s3 = fmaf(-2.f, acc[mt][nt][3], e21);
                if (s0 < best[2 * mt]) { best[2 * mt] = s0; bidx[2 * mt] = kc; }
                if (s1 < best[2 * mt]) { best[2 * mt] = s1; bidx[2 * mt] = kc + 1; }
                if (s2 < best[2 * mt + 1]) { best[2 * mt + 1] = s2; bidx[2 * mt + 1] = kc; }
                if (s3 < best[2 * mt + 1]) { best[2 * mt + 1] = s3; bidx[2 * mt + 1] = kc + 1; }
            }
        }
    }

    // reduce across the 4 lanes of each quad (same rows, different cols)
#pragma unroll
    for (int s = 0; s < 4; ++s) {
        float v = best[s];
        int ix = bidx[s];
#pragma unroll
        for (int off = 1; off <= 2; off <<= 1) {
            float v2 = __shfl_xor_sync(0xFFFFFFFFu, v, off);
            int i2 = __shfl_xor_sync(0xFFFFFFFFu, ix, off);
            if (v2 < v || (v2 == v && i2 < ix)) { v = v2; ix = i2; }
        }
        if (tig == 0) {
            int row = mbw + (s >> 1) * 16 + gid + (s & 1) * 8;
            redv[row][wn] = v;
            redi[row][wn] = ix;
        }
    }
    __syncthreads();
    if (tid < BM) {
        float bv = redv[tid][0];
        int bi = redi[tid][0];
#pragma unroll
        for (int t = 1; t < 4; ++t) {
            float v = redv[tid][t];
            int id = redi[tid][t];
            if (v < bv || (v == bv && id < bi)) { bv = v; bi = id; }
        }
        idx_s[tid] = bi;
        if (has_idx) idx_out[n0 + tid] = (float)bi;
    }
    __syncthreads();

    // gather nearest code (exact fp32), scatter to (B,D,H,W)
    for (int r = tid; r < D_DIM * BM; r += THREADS) {
        int d = r >> 7;
        int m = r & (BM - 1);
        out[((size_t)b * D_DIM + d) * 1024 + hw0 + m] = emb[(size_t)d * K_DIM + idx_s[m]];
    }
}

extern "C" void kernel_launch(void* const* d_in, const int* in_sizes, int n_in,
                              void* d_out, int out_size) {
    const float* x = (const float*)d_in[0];    // (64,256,32,32)
    const float* emb = (const float*)d_in[1];  // (256,1024)
    float* out = (float*)d_out;

    const int n_img = 64 * 256 * 32 * 32;
    const int n_lat = 64 * 32 * 32;
    float* idx_out = nullptr;
    int has_idx = 0;
    if (out_size >= n_img + n_lat) {
        idx_out = out + n_img;
        has_idx = 1;
    }

    cudaFuncSetAttribute(vq_mma_kernel, cudaFuncAttributeMaxDynamicSharedMemorySize, SMEM_DYN);

    float* xhi; cudaGetSymbolAddress((void**)&xhi, g_xhi);
    float* xlo; cudaGetSymbolAddress((void**)&xlo, g_xlo);
    float* ehi; cudaGetSymbolAddress((void**)&ehi, g_ehi);
    float* elo; cudaGetSymbolAddress((void**)&elo, g_elo);

    e2_kernel<<<4, 256>>>(emb);
    cvt_kernel<<<n_img / 1024, 256>>>(x, xhi, xlo);
    cvt_kernel<<<(D_DIM * K_DIM) / 1024, 256>>>(emb, ehi, elo);
    vq_mma_kernel<<<512, THREADS, SMEM_DYN>>>(emb, out, idx_out, has_idx);
}

// round 11
// speedup vs baseline: 1.8415x; 1.0290x over previous
#include <cuda_runtime.h>
#include <cstdint>
#include <math_constants.h>

// NearestEmbed via mma.sync tf32 (3xTF32 split) + fused argmin epilogue.
// R11 = R9 + pre-packed fragment layouts (LDS.128/LDS.64 fragment loads,
// 48 LDS/chunk vs 128) + 3-stage cp.async pipeline with 1 barrier/chunk.
// score[n,k] = ||e_k||^2 - 2 * x_n . e_k
// dot = xhi.ehi + xhi.elo + xlo.ehi  (tf32 split, fp32 accumulate)

#define D_DIM 256
#define K_DIM 1024
#define BM 128
#define BN 128
#define THREADS 512
#define NCHUNK 64                       // 8 k-tiles x 8 d-chunks

#define SEC_FLOATS 4096                 // one packed array chunk = 16KB
#define BUF_FLOATS (4 * SEC_FLOATS)     // Ah, Al, Bh, Bl = 64KB
#define SMEM_DYN (3 * BUF_FLOATS * 4)   // 196608 bytes

__device__ float g_e2[K_DIM];
__device__ float g_pAh[512 * 8 * SEC_FLOATS];   // [tile][ch][g][mp][tig] float4
__device__ float g_pAl[512 * 8 * SEC_FLOATS];
__device__ float g_pBh[64 * SEC_FLOATS];        // [kt*8+ch][g][n][tig] float2
__device__ float g_pBl[64 * SEC_FLOATS];

__device__ __forceinline__ uint32_t to_tf32(float f) {
    uint32_t r;
    asm("cvt.rna.tf32.f32 %0, %1;" : "=r"(r) : "f"(f));
    return r;
}

__device__ __forceinline__ uint32_t smem_u32(const void* p) {
    uint32_t a;
    asm("{ .reg .u64 t; cvta.to.shared.u64 t, %1; cvt.u32.u64 %0, t; }" : "=r"(a) : "l"(p));
    return a;
}

__device__ __forceinline__ void cp16(uint32_t dst, const void* src) {
    asm volatile("cp.async.cg.shared.global [%0], [%1], 16;" :: "r"(dst), "l"(src) : "memory");
}
#define CP_COMMIT() asm volatile("cp.async.commit_group;" ::: "memory")
#define CP_WAIT(N)  asm volatile("cp.async.wait_group %0;" :: "n"(N) : "memory")

__device__ __forceinline__ void mma8(float* c, uint4 a, uint2 b) {
    asm volatile(
        "mma.sync.aligned.m16n8k8.row.col.f32.tf32.tf32.f32 "
        "{%0,%1,%2,%3}, {%4,%5,%6,%7}, {%8,%9}, {%0,%1,%2,%3};"
        : "+f"(c[0]), "+f"(c[1]), "+f"(c[2]), "+f"(c[3])
        : "r"(a.x), "r"(a.y), "r"(a.z), "r"(a.w), "r"(b.x), "r"(b.y));
}

// ---------------- prep kernels ----------------
__global__ void e2_kernel(const float* __restrict__ emb) {
    int k = blockIdx.x * blockDim.x + threadIdx.x;
    float s = 0.f;
#pragma unroll 8
    for (int d = 0; d < D_DIM; ++d) {
        float v = emb[(size_t)d * K_DIM + k];
        s = fmaf(v, v, s);
    }
    g_e2[k] = s;
}

// pack x into fragment-order A chunks: tile = 128 latents, ch = 32 d's
__global__ void packA_kernel(const float* __restrict__ x) {
    __shared__ float xs[32 * 128];
    const int ch = blockIdx.x;
    const int tile = blockIdx.y;
    const int b = tile >> 3;
    const int hw0 = (tile & 7) << 7;
    const int tid = threadIdx.x;
    const float* xb = x + ((size_t)b * D_DIM + ch * 32) * 1024 + hw0;
#pragma unroll
    for (int i = 0; i < 4; ++i) {
        int f = tid + i * 256;
        int r = f >> 5, q = (f & 31) << 2;
        *(float4*)&xs[r * 128 + q] = *(const float4*)(xb + (size_t)r * 1024 + q);
    }
    __syncthreads();
    float4* dh = (float4*)g_pAh + (size_t)(tile * 8 + ch) * 1024;
    float4* dl = (float4*)g_pAl + (size_t)(tile * 8 + ch) * 1024;
#pragma unroll
    for (int i = 0; i < 4; ++i) {
        int o = tid + i * 256;                  // [g][mp][tig]
        int tig = o & 3, mp = (o >> 2) & 63, g = o >> 8;
        int k = g * 8 + tig;
        int M0 = ((mp & 0x38) << 1) | (mp & 7);
        float v0 = xs[k * 128 + M0];
        float v1 = xs[k * 128 + M0 + 8];
        float v2 = xs[(k + 4) * 128 + M0];
        float v3 = xs[(k + 4) * 128 + M0 + 8];
        float4 h, l;
        h.x = __uint_as_float(to_tf32(v0)); l.x = __uint_as_float(to_tf32(v0 - h.x));
        h.y = __uint_as_float(to_tf32(v1)); l.y = __uint_as_float(to_tf32(v1 - h.y));
        h.z = __uint_as_float(to_tf32(v2)); l.z = __uint_as_float(to_tf32(v2 - h.z));
        h.w = __uint_as_float(to_tf32(v3)); l.w = __uint_as_float(to_tf32(v3 - h.w));
        dh[o] = h;
        dl[o] = l;
    }
}

// pack emb into fragment-order B chunks: c = kt*8+ch
__global__ void packB_kernel(const float* __restrict__ emb) {
    const int c = blockIdx.x;
    const int kt = c >> 3, ch = c & 7;
    const int k0 = kt * BN, d0 = ch * 32;
    const int tid = threadIdx.x;
    float2* dh = (float2*)g_pBh + (size_t)c * 2048;
    float2* dl = (float2*)g_pBl + (size_t)c * 2048;
#pragma unroll
    for (int i = 0; i < 8; ++i) {
        int o = tid + i * 256;                  // [g][n][tig]
        int tig = o & 3, n = (o >> 2) & 127, g = o >> 9;
        int k = d0 + g * 8 + tig;
        float v0 = emb[(size_t)k * K_DIM + k0 + n];
        float v1 = emb[(size_t)(k + 4) * K_DIM + k0 + n];
        float2 h, l;
        h.x = __uint_as_float(to_tf32(v0)); l.x = __uint_as_float(to_tf32(v0 - h.x));
        h.y = __uint_as_float(to_tf32(v1)); l.y = __uint_as_float(to_tf32(v1 - h.y));
        dh[o] = h;
        dl[o] = l;
    }
}

// ---------------- main kernel ----------------
__global__ __launch_bounds__(THREADS, 1)
void vq_mma_kernel(const float* __restrict__ emb, float* __restrict__ out,
                   float* __restrict__ idx_out, int has_idx) {
    extern __shared__ float sm[];
    __shared__ float e2s[K_DIM];
    __shared__ float redv[BM][4];
    __shared__ int redi[BM][4];
    __shared__ int idx_s[BM];

    const int tid = threadIdx.x;
    const int wid = tid >> 5;
    const int lane = tid & 31;
    const int gid = lane >> 2;
    const int tig = lane & 3;
    const int wm = wid >> 2;
    const int wn = wid & 3;
    const int mbw = wm * 32;
    const int nbw = wn * 32;
    const uint32_t smb = smem_u32(sm);

    const int tile = blockIdx.x;
    const int n0 = tile * BM;
    const int b = n0 >> 10;
    const int hw0 = n0 & 1023;

    // staging lambda: chunk c -> buffer c%3 (pure linear 16B copies)
    auto stage = [&](int c) {
        const uint32_t base = smb + (uint32_t)(c % 3) * (BUF_FLOATS * 4);
        const float* sAh = g_pAh + (size_t)(tile * 8 + (c & 7)) * SEC_FLOATS;
        const float* sAl = g_pAl + (size_t)(tile * 8 + (c & 7)) * SEC_FLOATS;
        const float* sBh = g_pBh + (size_t)c * SEC_FLOATS;
        const float* sBl = g_pBl + (size_t)c * SEC_FLOATS;
#pragma unroll
        for (int i = 0; i < 2; ++i) {
            int t = tid + i * THREADS;          // float4 index 0..1023
            cp16(base + t * 16, sAh + t * 4);
            cp16(base + SEC_FLOATS * 4 + t * 16, sAl + t * 4);
            cp16(base + SEC_FLOATS * 8 + t * 16, sBh + t * 4);
            cp16(base + SEC_FLOATS * 12 + t * 16, sBl + t * 4);
        }
    };

    for (int i = tid; i < K_DIM; i += THREADS) e2s[i] = g_e2[i];

    float best[4];
    int bidx[4];
#pragma unroll
    for (int s = 0; s < 4; ++s) { best[s] = CUDART_INF_F; bidx[s] = 0; }

    stage(0); CP_COMMIT();
    stage(1); CP_COMMIT();

    float acc[2][4][4];
    const int a0i = (gid + wm * 16) * 4 + tig;       // mt=0 fragment index
    const int a1i = (gid + 8 + wm * 16) * 4 + tig;   // mt=1
    const int bbase = (nbw + gid) * 4 + tig;

    for (int c = 0; c < NCHUNK; ++c) {
        if ((c & 7) == 0) {
#pragma unroll
            for (int mt = 0; mt < 2; ++mt)
#pragma unroll
                for (int nt = 0; nt < 4; ++nt)
#pragma unroll
                    for (int j = 0; j < 4; ++j) acc[mt][nt][j] = 0.f;
        }

        if (c < NCHUNK - 1) { CP_WAIT(1); } else { CP_WAIT(0); }
        __syncthreads();
        if (c + 2 < NCHUNK) { stage(c + 2); CP_COMMIT(); }

        const float* buf = sm + (c % 3) * BUF_FLOATS;
        const uint4* Ah = (const uint4*)buf;
        const uint4* Al = (const uint4*)(buf + SEC_FLOATS);
        const uint2* Bh = (const uint2*)(buf + 2 * SEC_FLOATS);
        const uint2* Bl = (const uint2*)(buf + 3 * SEC_FLOATS);

#pragma unroll
        for (int g = 0; g < 4; ++g) {
            uint4 ah0 = Ah[g * 256 + a0i];
            uint4 ah1 = Ah[g * 256 + a1i];
            uint4 al0 = Al[g * 256 + a0i];
            uint4 al1 = Al[g * 256 + a1i];
#pragma unroll
            for (int nt = 0; nt < 4; ++nt) {
                uint2 bh = Bh[g * 512 + bbase + nt * 32];
                uint2 bl = Bl[g * 512 + bbase + nt * 32];
                mma8(acc[0][nt], ah0, bh);
                mma8(acc[0][nt], ah0, bl);
                mma8(acc[0][nt], al0, bh);
                mma8(acc[1][nt], ah1, bh);
                mma8(acc[1][nt], ah1, bl);
                mma8(acc[1][nt], al1, bh);
            }
        }

        if ((c & 7) == 7) {
            // fused argmin epilogue for k-tile kt = c>>3 (registers only)
            const int k0 = (c >> 3) * BN;
#pragma unroll
            for (int mt = 0; mt < 2; ++mt) {
#pragma unroll
                for (int nt = 0; nt < 4; ++nt) {
                    const int kc = k0 + nbw + nt * 8 + 2 * tig;
                    const float e20 = e2s[kc], e21 = e2s[kc + 1];
                    float s0 = fmaf(-2.f, acc[mt][nt][0], e20);
                    float s1 = fmaf(-2.f, acc[mt][nt][1], e21);
                    float s2 = fmaf(-2.f, acc[mt][nt][2], e20);
                    float s3 = fmaf(-2.f, acc[mt][nt][3], e21);
                    if (s0 < best[2 * mt]) { best[2 * mt] = s0; bidx[2 * mt] = kc; }
                    if (s1 < best[2 * mt]) { best[2 * mt] = s1; bidx[2 * mt] = kc + 1; }
                    if (s2 < best[2 * mt + 1]) { best[2 * mt + 1] = s2; bidx[2 * mt + 1] = kc; }
                    if (s3 < best[2 * mt + 1]) { best[2 * mt + 1] = s3; bidx[2 * mt + 1] = kc + 1; }
                }
            }
        }
    }

    // reduce across the 4 lanes of each quad (same rows, different cols)
#pragma unroll
    for (int s = 0; s < 4; ++s) {
        float v = best[s];
        int ix = bidx[s];
#pragma unroll
        for (int off = 1; off <= 2; off <<= 1) {
            float v2 = __shfl_xor_sync(0xFFFFFFFFu, v, off);
            int i2 = __shfl_xor_sync(0xFFFFFFFFu, ix, off);
            if (v2 < v || (v2 == v && i2 < ix)) { v = v2; ix = i2; }
        }
        if (tig == 0) {
            int row = mbw + (s >> 1) * 16 + gid + (s & 1) * 8;
            redv[row][wn] = v;
            redi[row][wn] = ix;
        }
    }
    __syncthreads();
    if (tid < BM) {
        float bv = redv[tid][0];
        int bi = redi[tid][0];
#pragma unroll
        for (int t = 1; t < 4; ++t) {
            float v = redv[tid][t];
            int id = redi[tid][t];
            if (v < bv || (v == bv && id < bi)) { bv = v; bi = id; }
        }
        idx_s[tid] = bi;
        if (has_idx) idx_out[n0 + tid] = (float)bi;
    }
    __syncthreads();

    // gather nearest code (exact fp32), scatter to (B,D,H,W)
    for (int r = tid; r < D_DIM * BM; r += THREADS) {
        int d = r >> 7;
        int m = r & (BM - 1);
        out[((size_t)b * D_DIM + d) * 1024 + hw0 + m] = emb[(size_t)d * K_DIM + idx_s[m]];
    }
}

extern "C" void kernel_launch(void* const* d_in, const int* in_sizes, int n_in,
                              void* d_out, int out_size) {
    const float* x = (const float*)d_in[0];    // (64,256,32,32)
    const float* emb = (const float*)d_in[1];  // (256,1024)
    float* out = (float*)d_out;

    const int n_img = 64 * 256 * 32 * 32;
    const int n_lat = 64 * 32 * 32;
    float* idx_out = nullptr;
    int has_idx = 0;
    if (out_size >= n_img + n_lat) {
        idx_out = out + n_img;
        has_idx = 1;
    }

    cudaFuncSetAttribute(vq_mma_kernel, cudaFuncAttributeMaxDynamicSharedMemorySize, SMEM_DYN);

    e2_kernel<<<4, 256>>>(emb);
    packA_kernel<<<dim3(8, 512), 256>>>(x);
    packB_kernel<<<64, 256>>>(emb);
    vq_mma_kernel<<<512, THREADS, SMEM_DYN>>>(emb, out, idx_out, has_idx);
}